// round 7
// baseline (speedup 1.0000x reference)
#include <cuda_runtime.h>
#include <cuda_fp16.h>
#include <cstdint>

// Problem constants (B=4, S=2048, EMB=1024, HEADS=16, HEAD_DIM=64)
#define TOK   8192
#define EMB_  1024
#define NHEAD 16
#define HDIM  64
#define TILEB 16384          // one 128-row x 128-byte (64 fp16) tile

// ---------------------------------------------------------------------------
// Scratch (device globals). Tiled-swizzled fp16:
// element (row, col) -> tile (row>>7, col>>6), inside: byte
//   (row&127)*128 + (((col&63)>>3) ^ (row&7))*16 + (col&7)*2
// ---------------------------------------------------------------------------
__device__ __half g_vhi[TOK * EMB_], g_vlo[TOK * EMB_];
__device__ __half g_khi[TOK * EMB_], g_klo[TOK * EMB_];
__device__ __half g_qhi[TOK * EMB_], g_qlo[TOK * EMB_];
__device__ __half g_wvhi[EMB_ * EMB_];
__device__ __half g_wkhi[EMB_ * EMB_];
__device__ __half g_wqhi[EMB_ * EMB_];
__device__ __half g_wohi[EMB_ * EMB_];
__device__ __half g_ahi[TOK * EMB_], g_alo[TOK * EMB_];
__device__ float g_v[TOK * EMB_], g_k[TOK * EMB_], g_q[TOK * EMB_];

// ---------------------------------------------------------------------------
// PTX helpers
// ---------------------------------------------------------------------------
__device__ __forceinline__ uint32_t smem_u32(const void* p) {
    uint32_t a;
    asm("{ .reg .u64 t; cvta.to.shared.u64 t, %1; cvt.u32.u64 %0, t; }"
        : "=r"(a) : "l"(p));
    return a;
}

#define MBAR_INIT(addr, cnt) \
    asm volatile("mbarrier.init.shared.b64 [%0], %1;" :: "r"(addr), "r"(cnt) : "memory")
#define MBAR_EXPECT_TX(addr, bytes) \
    asm volatile("mbarrier.arrive.expect_tx.shared.b64 _, [%0], %1;" \
                 :: "r"(addr), "r"(bytes) : "memory")
#define MBAR_WAIT(addr, parity) do { \
    uint32_t _m = (addr), _p = (parity), _done; \
    asm volatile("{ .reg .pred p; mbarrier.try_wait.parity.acquire.cta.shared::cta.b64 p, [%1], %2; selp.b32 %0, 1, 0, p; }" \
                 : "=r"(_done) : "r"(_m), "r"(_p) : "memory"); \
    if (!_done) { \
        asm volatile("{ .reg .pred P1; WL_%=: mbarrier.try_wait.parity.acquire.cta.shared::cta.b64 P1, [%0], %1, 0x989680; @P1 bra.uni WD_%=; bra.uni WL_%=; WD_%=: }" \
                     :: "r"(_m), "r"(_p) : "memory"); \
    } \
} while (0)

__device__ __forceinline__ void bulk_g2s(uint32_t dst, const void* src,
                                         uint32_t bytes, uint32_t mbar) {
    asm volatile(
        "cp.async.bulk.shared::cluster.global.mbarrier::complete_tx::bytes [%0], [%1], %2, [%3];"
        :: "r"(dst), "l"(src), "r"(bytes), "r"(mbar) : "memory");
}

#define LDSM4(R, addr) \
    asm volatile("ldmatrix.sync.aligned.m8n8.x4.shared.b16 {%0,%1,%2,%3}, [%4];" \
        : "=r"((R)[0]), "=r"((R)[1]), "=r"((R)[2]), "=r"((R)[3]) : "r"(addr))

#define MMA16816(D, A, B0, B1) \
    asm volatile("mma.sync.aligned.m16n8k16.row.col.f32.f16.f16.f32 " \
        "{%0,%1,%2,%3}, {%4,%5,%6,%7}, {%8,%9}, {%0,%1,%2,%3};" \
        : "+f"((D)[0]), "+f"((D)[1]), "+f"((D)[2]), "+f"((D)[3]) \
        : "r"((A)[0]), "r"((A)[1]), "r"((A)[2]), "r"((A)[3]), "r"(B0), "r"(B1))

// ---------------------------------------------------------------------------
// Conversions: fp32 row-major -> fp16 hi(/lo) in tiled-swizzled layout.
// ---------------------------------------------------------------------------
__device__ __forceinline__ void split_store(const float* __restrict__ src,
                                            __half* __restrict__ hi,
                                            __half* __restrict__ lo, int gid)
{
    const int row = gid >> 7;
    const int chunk = gid & 127;
    const int col0 = chunk << 3;
    const int kc = col0 >> 6;
    const int c16 = (col0 >> 3) & 7;

    const float4* sp = (const float4*)(src + (size_t)row * EMB_ + col0);
    float x[8];
    *(float4*)&x[0] = sp[0];
    *(float4*)&x[4] = sp[1];

    uint32_t hw[4], lw[4];
#pragma unroll
    for (int i = 0; i < 4; i++) {
        __half h0 = __float2half_rn(x[2 * i]);
        __half h1 = __float2half_rn(x[2 * i + 1]);
        hw[i] = (uint32_t)__half_as_ushort(h0) | ((uint32_t)__half_as_ushort(h1) << 16);
        if (lo) {
            __half l0 = __float2half_rn(x[2 * i]     - __half2float(h0));
            __half l1 = __float2half_rn(x[2 * i + 1] - __half2float(h1));
            lw[i] = (uint32_t)__half_as_ushort(l0) | ((uint32_t)__half_as_ushort(l1) << 16);
        }
    }
    const size_t off = (((size_t)(row >> 7) * 16 + kc) << 14)
                     + (row & 127) * 128 + ((c16 ^ (row & 7)) << 4);
    *(uint4*)((char*)hi + off) = make_uint4(hw[0], hw[1], hw[2], hw[3]);
    if (lo)
        *(uint4*)((char*)lo + off) = make_uint4(lw[0], lw[1], lw[2], lw[3]);
}

struct ConvArgs {
    const float* src[4];
    __half* hi[4];
    __half* lo[4];
};

__global__ __launch_bounds__(256)
void conv_act(ConvArgs a)   // grid (4096, 3): activations, split
{
    const int z = blockIdx.y;
    const int gid = blockIdx.x * 256 + threadIdx.x;
    split_store(a.src[z], a.hi[z], a.lo[z], gid);
}

__global__ __launch_bounds__(256)
void conv_w(ConvArgs a)     // grid (512, 4): all weights round-only
{
    const int z = blockIdx.y;
    const int gid = blockIdx.x * 256 + threadIdx.x;
    split_store(a.src[z], a.hi[z], nullptr, gid);
}

// ---------------------------------------------------------------------------
// 2-term split-fp16 HMMA GEMM: C ~= (Ah+Al)·Bh^T + bias
// Tile 128m x 256n, K-chunk 64, 3-stage bulk-copy pipeline.
// 512 threads = 16 warps in 4m x 4n; warp tile 32m x 64n.
// Stage = Ah(16K) + Al(16K) + Bh(2 x 16K) = 64KB.
// ---------------------------------------------------------------------------
#define STAGEB (4 * TILEB)              // 65536
#define GSMEM  (1024 + 3 * STAGEB)      // 197632

__device__ __forceinline__
void gemm_core2(const __half* __restrict__ Ah, const __half* __restrict__ Al,
                const __half* __restrict__ Bh,
                const float* __restrict__ bias, float* __restrict__ C,
                char* smem)
{
    const uint32_t sb = smem_u32(smem);
    const int tid = threadIdx.x;
    const int wid = tid >> 5, lane = tid & 31;
    const int ntb = blockIdx.x, mtb = blockIdx.y;
    const int wm = wid >> 2, wn = wid & 3;

    if (tid == 0) {
        MBAR_INIT(sb + 0, 1);
        MBAR_INIT(sb + 8, 1);
        MBAR_INIT(sb + 16, 1);
    }
    __syncthreads();

    const uint32_t st0 = sb + 1024;
    const char* aH = (const char*)Ah + ((size_t)mtb * 16 << 14);
    const char* aL = (const char*)Al + ((size_t)mtb * 16 << 14);
    const char* bH0 = (const char*)Bh + ((size_t)(ntb * 2 + 0) * 16 << 14);
    const char* bH1 = (const char*)Bh + ((size_t)(ntb * 2 + 1) * 16 << 14);

    auto load_stage = [&](int kc, int s) {
        const uint32_t full = sb + 8 * s;
        MBAR_EXPECT_TX(full, STAGEB);
        const uint32_t d = st0 + s * STAGEB;
        const size_t o = (size_t)kc << 14;
        bulk_g2s(d + 0 * TILEB, aH + o, TILEB, full);
        bulk_g2s(d + 1 * TILEB, aL + o, TILEB, full);
        bulk_g2s(d + 2 * TILEB, bH0 + o, TILEB, full);
        bulk_g2s(d + 3 * TILEB, bH1 + o, TILEB, full);
    };

    if (tid == 0) {
        load_stage(0, 0);
        load_stage(1, 1);
        load_stage(2, 2);
    }

    float acc[2][8][4];
#pragma unroll
    for (int a = 0; a < 2; a++)
#pragma unroll
        for (int b = 0; b < 8; b++)
#pragma unroll
            for (int c = 0; c < 4; c++) acc[a][b][c] = 0.0f;

    const uint32_t la7 = lane & 7;
    const uint32_t a_row = (uint32_t)(wm * 32 + (lane & 15)) * 128;
    const uint32_t a_sel = (lane >> 4);
    // warp covers n = wn*64 .. +63 of 256; B tile index = wn>>1, 64-row half = wn&1
    const uint32_t b_tile_off = (uint32_t)(2 + (wn >> 1)) * TILEB;
    const uint32_t b_row = (uint32_t)((wn & 1) * 64 + ((lane >> 4) & 1) * 8 + (lane & 7)) * 128;
    const uint32_t b_sel = ((lane >> 3) & 1);

    int s = 0, par = 0;
    for (int kc = 0; kc < 16; kc++) {
        MBAR_WAIT(sb + 8 * s, par);

        const uint32_t st = st0 + s * STAGEB;
        const uint32_t tAH = st + 0 * TILEB;
        const uint32_t tAL = st + 1 * TILEB;
        const uint32_t tBH = st + b_tile_off;

#pragma unroll
        for (int ks = 0; ks < 4; ks++) {
            const uint32_t ca = ((uint32_t)(ks * 2) + a_sel) ^ la7;
            const uint32_t cb = ((uint32_t)(ks * 2) + b_sel) ^ la7;
            uint32_t ah[2][4], al[2][4], bh[4][4];
#pragma unroll
            for (int m2 = 0; m2 < 2; m2++) {
                LDSM4(ah[m2], tAH + a_row + m2 * 2048 + ca * 16);
                LDSM4(al[m2], tAL + a_row + m2 * 2048 + ca * 16);
            }
#pragma unroll
            for (int n2 = 0; n2 < 4; n2++)
                LDSM4(bh[n2], tBH + b_row + n2 * 2048 + cb * 16);
#pragma unroll
            for (int m2 = 0; m2 < 2; m2++)
#pragma unroll
                for (int n2 = 0; n2 < 4; n2++) {
                    MMA16816(acc[m2][n2 * 2 + 0], ah[m2], bh[n2][0], bh[n2][1]);
                    MMA16816(acc[m2][n2 * 2 + 1], ah[m2], bh[n2][2], bh[n2][3]);
                    MMA16816(acc[m2][n2 * 2 + 0], al[m2], bh[n2][0], bh[n2][1]);
                    MMA16816(acc[m2][n2 * 2 + 1], al[m2], bh[n2][2], bh[n2][3]);
                }
        }
        __syncthreads();
        if (tid == 0 && kc + 3 < 16) load_stage(kc + 3, s);
        if (++s == 3) { s = 0; par ^= 1; }
    }

    const int rbase = mtb * 128 + wm * 32 + (lane >> 2);
    const int cbase = ntb * 256 + wn * 64 + (lane & 3) * 2;
#pragma unroll
    for (int m2 = 0; m2 < 2; m2++)
#pragma unroll
        for (int nt2 = 0; nt2 < 8; nt2++) {
            const int col = cbase + nt2 * 8;
            const float b0 = bias[col], b1 = bias[col + 1];
            float* p0 = C + (size_t)(rbase + m2 * 16) * EMB_ + col;
            float* p1 = p0 + 8 * EMB_;
            *(float2*)p0 = make_float2(acc[m2][nt2][0] + b0, acc[m2][nt2][1] + b1);
            *(float2*)p1 = make_float2(acc[m2][nt2][2] + b0, acc[m2][nt2][3] + b1);
        }
}

struct QKVArgs {
    const __half* ah[3];
    const __half* al[3];
    const __half* bh[3];
    const float*  bias[3];
    float*        c[3];
};

__global__ __launch_bounds__(512, 1)
void gemm_qkv(QKVArgs a)
{
    extern __shared__ char smem[];
    const int z = blockIdx.z;
    gemm_core2(a.ah[z], a.al[z], a.bh[z], a.bias[z], a.c[z], smem);
}

__global__ __launch_bounds__(512, 1)
void gemm_o(const __half* __restrict__ ah, const __half* __restrict__ al,
            const __half* __restrict__ bh, const float* __restrict__ bias,
            float* __restrict__ c)
{
    extern __shared__ char smem[];
    gemm_core2(ah, al, bh, bias, c, smem);
}

// ---------------------------------------------------------------------------
// Per-token head-axis attention (fp32 in, tiled-swizzled fp16 hi/lo out).
// ---------------------------------------------------------------------------
__global__ __launch_bounds__(256)
void attn_head_mix(const float* __restrict__ q, const float* __restrict__ k,
                   const float* __restrict__ v,
                   __half* __restrict__ ohi, __half* __restrict__ olo)
{
    __shared__ float sq[NHEAD][68];
    __shared__ float skT[HDIM][18];
    __shared__ float sv[NHEAD][68];
    __shared__ float sa[NHEAD * NHEAD];

    const int t = blockIdx.x;
    const int tid = threadIdx.x;
    const size_t base = (size_t)t * EMB_;

    {
        const int e0 = tid * 4;
        const int h = e0 >> 6, d0 = e0 & 63;
        float4 q4 = *(const float4*)(q + base + e0);
        float4 k4 = *(const float4*)(k + base + e0);
        float4 v4 = *(const float4*)(v + base + e0);
        *(float4*)&sq[h][d0] = q4;
        *(float4*)&sv[h][d0] = v4;
        skT[d0 + 0][h] = k4.x;
        skT[d0 + 1][h] = k4.y;
        skT[d0 + 2][h] = k4.z;
        skT[d0 + 3][h] = k4.w;
    }
    __syncthreads();

    if (tid < 64) {
        const int h0 = (tid >> 3) << 1;
        const int g0 = (tid & 7) << 1;
        float s00 = 0.f, s01 = 0.f, s10 = 0.f, s11 = 0.f;
#pragma unroll
        for (int d = 0; d < HDIM; d += 2) {
            const float2 q0 = *(const float2*)&sq[h0][d];
            const float2 q1 = *(const float2*)&sq[h0 + 1][d];
            const float2 ka = *(const float2*)&skT[d][g0];
            const float2 kb = *(const float2*)&skT[d + 1][g0];
            s00 = fmaf(q0.x, ka.x, s00); s00 = fmaf(q0.y, kb.x, s00);
            s01 = fmaf(q0.x, ka.y, s01); s01 = fmaf(q0.y, kb.y, s01);
            s10 = fmaf(q1.x, ka.x, s10); s10 = fmaf(q1.y, kb.x, s10);
            s11 = fmaf(q1.x, ka.y, s11); s11 = fmaf(q1.y, kb.y, s11);
        }
        s00 *= 0.125f; s01 *= 0.125f; s10 *= 0.125f; s11 *= 0.125f;

        float m0 = fmaxf(s00, s01), m1 = fmaxf(s10, s11);
#pragma unroll
        for (int o = 4; o > 0; o >>= 1) {
            m0 = fmaxf(m0, __shfl_xor_sync(0xffffffffu, m0, o, 8));
            m1 = fmaxf(m1, __shfl_xor_sync(0xffffffffu, m1, o, 8));
        }
        const float e00 = __expf(s00 - m0), e01 = __expf(s01 - m0);
        const float e10 = __expf(s10 - m1), e11 = __expf(s11 - m1);
        float u0 = e00 + e01, u1 = e10 + e11;
#pragma unroll
        for (int o = 4; o > 0; o >>= 1) {
            u0 += __shfl_xor_sync(0xffffffffu, u0, o, 8);
            u1 += __shfl_xor_sync(0xffffffffu, u1, o, 8);
        }
        const float r0 = 1.0f / u0, r1 = 1.0f / u1;
        sa[h0 * 16 + g0]           = e00 * r0;
        sa[h0 * 16 + g0 + 1]       = e01 * r0;
        sa[(h0 + 1) * 16 + g0]     = e10 * r1;
        sa[(h0 + 1) * 16 + g0 + 1] = e11 * r1;
    }
    __syncthreads();

    const int ho = tid >> 4;
    const int d0 = (tid & 15) * 4;
    float o4[4] = {0.f, 0.f, 0.f, 0.f};
#pragma unroll
    for (int gg = 0; gg < NHEAD; gg++) {
        const float a = sa[ho * 16 + gg];
        float4 vv = *(const float4*)&sv[gg][d0];
        o4[0] = fmaf(a, vv.x, o4[0]);
        o4[1] = fmaf(a, vv.y, o4[1]);
        o4[2] = fmaf(a, vv.z, o4[2]);
        o4[3] = fmaf(a, vv.w, o4[3]);
    }

    ushort4 hv, lv;
    __half hb;
    hb = __float2half_rn(o4[0]); hv.x = __half_as_ushort(hb);
    lv.x = __half_as_ushort(__float2half_rn(o4[0] - __half2float(hb)));
    hb = __float2half_rn(o4[1]); hv.y = __half_as_ushort(hb);
    lv.y = __half_as_ushort(__float2half_rn(o4[1] - __half2float(hb)));
    hb = __float2half_rn(o4[2]); hv.z = __half_as_ushort(hb);
    lv.z = __half_as_ushort(__float2half_rn(o4[2] - __half2float(hb)));
    hb = __float2half_rn(o4[3]); hv.w = __half_as_ushort(hb);
    lv.w = __half_as_ushort(__float2half_rn(o4[3] - __half2float(hb)));

    const int chunk = d0 >> 3;
    const size_t off = (((size_t)(t >> 7) * 16 + ho) << 14)
                     + (t & 127) * 128 + ((chunk ^ (t & 7)) << 4) + (d0 & 7) * 2;
    *(ushort4*)((char*)ohi + off) = hv;
    *(ushort4*)((char*)olo + off) = lv;
}

// ---------------------------------------------------------------------------
// Launch
// ---------------------------------------------------------------------------
extern "C" void kernel_launch(void* const* d_in, const int* in_sizes, int n_in,
                              void* d_out, int out_size)
{
    const float* values = (const float*)d_in[0];
    const float* keys   = (const float*)d_in[1];
    const float* query  = (const float*)d_in[2];
    const float* Wv = (const float*)d_in[3];
    const float* bv = (const float*)d_in[4];
    const float* Wk = (const float*)d_in[5];
    const float* bk = (const float*)d_in[6];
    const float* Wq = (const float*)d_in[7];
    const float* bq = (const float*)d_in[8];
    const float* Wo = (const float*)d_in[9];
    const float* bo = (const float*)d_in[10];
    float* out = (float*)d_out;

    static bool attr_set = false;
    if (!attr_set) {
        cudaFuncSetAttribute(gemm_qkv,
                             cudaFuncAttributeMaxDynamicSharedMemorySize, GSMEM);
        cudaFuncSetAttribute(gemm_o,
                             cudaFuncAttributeMaxDynamicSharedMemorySize, GSMEM);
        attr_set = true;
    }

    __half *vhi, *vlo, *khi, *klo, *qhi, *qlo;
    __half *wvhi, *wkhi, *wqhi, *wohi;
    __half *ahi, *alo;
    float *gv, *gk, *gq;
    cudaGetSymbolAddress((void**)&vhi, g_vhi);   cudaGetSymbolAddress((void**)&vlo, g_vlo);
    cudaGetSymbolAddress((void**)&khi, g_khi);   cudaGetSymbolAddress((void**)&klo, g_klo);
    cudaGetSymbolAddress((void**)&qhi, g_qhi);   cudaGetSymbolAddress((void**)&qlo, g_qlo);
    cudaGetSymbolAddress((void**)&wvhi, g_wvhi);
    cudaGetSymbolAddress((void**)&wkhi, g_wkhi);
    cudaGetSymbolAddress((void**)&wqhi, g_wqhi);
    cudaGetSymbolAddress((void**)&wohi, g_wohi);
    cudaGetSymbolAddress((void**)&ahi, g_ahi);   cudaGetSymbolAddress((void**)&alo, g_alo);
    cudaGetSymbolAddress((void**)&gv, g_v);
    cudaGetSymbolAddress((void**)&gk, g_k);
    cudaGetSymbolAddress((void**)&gq, g_q);

    ConvArgs ca;
    ca.src[0] = values; ca.hi[0] = vhi; ca.lo[0] = vlo;
    ca.src[1] = keys;   ca.hi[1] = khi; ca.lo[1] = klo;
    ca.src[2] = query;  ca.hi[2] = qhi; ca.lo[2] = qlo;
    ca.src[3] = nullptr; ca.hi[3] = nullptr; ca.lo[3] = nullptr;
    conv_act<<<dim3(TOK * 128 / 256, 3), 256>>>(ca);

    ConvArgs cw;
    cw.src[0] = Wq; cw.hi[0] = wqhi; cw.lo[0] = nullptr;
    cw.src[1] = Wk; cw.hi[1] = wkhi; cw.lo[1] = nullptr;
    cw.src[2] = Wv; cw.hi[2] = wvhi; cw.lo[2] = nullptr;
    cw.src[3] = Wo; cw.hi[3] = wohi; cw.lo[3] = nullptr;
    conv_w<<<dim3(EMB_ * 128 / 256, 4), 256>>>(cw);

    QKVArgs a;
    a.ah[0] = qhi; a.al[0] = qlo; a.bh[0] = wqhi; a.bias[0] = bq; a.c[0] = gq;
    a.ah[1] = khi; a.al[1] = klo; a.bh[1] = wkhi; a.bias[1] = bk; a.c[1] = gk;
    a.ah[2] = vhi; a.al[2] = vlo; a.bh[2] = wvhi; a.bias[2] = bv; a.c[2] = gv;
    dim3 ggrid(EMB_ / 256, TOK / 128, 3);   // (4, 64, 3)
    gemm_qkv<<<ggrid, 512, GSMEM>>>(a);

    attn_head_mix<<<TOK, 256>>>(gq, gk, gv, ahi, alo);

    dim3 ogrid(EMB_ / 256, TOK / 128);      // (4, 64)
    gemm_o<<<ogrid, 512, GSMEM>>>(ahi, alo, wohi, bo, out);
}

// round 8
// speedup vs baseline: 1.7079x; 1.7079x over previous
#include <cuda_runtime.h>
#include <cuda_fp16.h>
#include <cstdint>

// Problem constants (B=4, S=2048, EMB=1024, HEADS=16, HEAD_DIM=64)
#define TOK   8192
#define EMB_  1024
#define NHEAD 16
#define HDIM  64
#define TILEB 16384          // one 128-row x 128-byte (64 fp16) tile

// ---------------------------------------------------------------------------
// Scratch (device globals). Tiled-swizzled fp16:
// element (row, col) -> tile (row>>7, col>>6), inside: byte
//   (row&127)*128 + (((col&63)>>3) ^ (row&7))*16 + (col&7)*2
// ---------------------------------------------------------------------------
__device__ __half g_vh[TOK * EMB_];
__device__ __half g_kh[TOK * EMB_];
__device__ __half g_qh[TOK * EMB_];
__device__ __half g_wvh[EMB_ * EMB_];
__device__ __half g_wkh[EMB_ * EMB_];
__device__ __half g_wqh[EMB_ * EMB_];
__device__ __half g_woh[EMB_ * EMB_];
__device__ __half g_ah[TOK * EMB_];
__device__ float g_v[TOK * EMB_], g_k[TOK * EMB_], g_q[TOK * EMB_];

// ---------------------------------------------------------------------------
// PTX helpers
// ---------------------------------------------------------------------------
__device__ __forceinline__ uint32_t smem_u32(const void* p) {
    uint32_t a;
    asm("{ .reg .u64 t; cvta.to.shared.u64 t, %1; cvt.u32.u64 %0, t; }"
        : "=r"(a) : "l"(p));
    return a;
}

#define MBAR_INIT(addr, cnt) \
    asm volatile("mbarrier.init.shared.b64 [%0], %1;" :: "r"(addr), "r"(cnt) : "memory")
#define MBAR_EXPECT_TX(addr, bytes) \
    asm volatile("mbarrier.arrive.expect_tx.shared.b64 _, [%0], %1;" \
                 :: "r"(addr), "r"(bytes) : "memory")
#define MBAR_WAIT(addr, parity) do { \
    uint32_t _m = (addr), _p = (parity), _done; \
    asm volatile("{ .reg .pred p; mbarrier.try_wait.parity.acquire.cta.shared::cta.b64 p, [%1], %2; selp.b32 %0, 1, 0, p; }" \
                 : "=r"(_done) : "r"(_m), "r"(_p) : "memory"); \
    if (!_done) { \
        asm volatile("{ .reg .pred P1; WL_%=: mbarrier.try_wait.parity.acquire.cta.shared::cta.b64 P1, [%0], %1, 0x989680; @P1 bra.uni WD_%=; bra.uni WL_%=; WD_%=: }" \
                     :: "r"(_m), "r"(_p) : "memory"); \
    } \
} while (0)

__device__ __forceinline__ void bulk_g2s(uint32_t dst, const void* src,
                                         uint32_t bytes, uint32_t mbar) {
    asm volatile(
        "cp.async.bulk.shared::cluster.global.mbarrier::complete_tx::bytes [%0], [%1], %2, [%3];"
        :: "r"(dst), "l"(src), "r"(bytes), "r"(mbar) : "memory");
}

#define LDSM4(R, addr) \
    asm volatile("ldmatrix.sync.aligned.m8n8.x4.shared.b16 {%0,%1,%2,%3}, [%4];" \
        : "=r"((R)[0]), "=r"((R)[1]), "=r"((R)[2]), "=r"((R)[3]) : "r"(addr))

#define MMA16816(D, A, B0, B1) \
    asm volatile("mma.sync.aligned.m16n8k16.row.col.f32.f16.f16.f32 " \
        "{%0,%1,%2,%3}, {%4,%5,%6,%7}, {%8,%9}, {%0,%1,%2,%3};" \
        : "+f"((D)[0]), "+f"((D)[1]), "+f"((D)[2]), "+f"((D)[3]) \
        : "r"((A)[0]), "r"((A)[1]), "r"((A)[2]), "r"((A)[3]), "r"(B0), "r"(B1))

// ---------------------------------------------------------------------------
// Conversion: fp32 row-major -> fp16 (round) in tiled-swizzled layout.
// One thread per 16B output chunk (8 cols).
// ---------------------------------------------------------------------------
__device__ __forceinline__ void round_store(const float* __restrict__ src,
                                            __half* __restrict__ hi, int gid)
{
    const int row = gid >> 7;
    const int chunk = gid & 127;
    const int col0 = chunk << 3;
    const int kc = col0 >> 6;
    const int c16 = (col0 >> 3) & 7;

    const float4* sp = (const float4*)(src + (size_t)row * EMB_ + col0);
    float x[8];
    *(float4*)&x[0] = sp[0];
    *(float4*)&x[4] = sp[1];

    uint32_t hw[4];
#pragma unroll
    for (int i = 0; i < 4; i++) {
        __half h0 = __float2half_rn(x[2 * i]);
        __half h1 = __float2half_rn(x[2 * i + 1]);
        hw[i] = (uint32_t)__half_as_ushort(h0) | ((uint32_t)__half_as_ushort(h1) << 16);
    }
    const size_t off = (((size_t)(row >> 7) * 16 + kc) << 14)
                     + (row & 127) * 128 + ((c16 ^ (row & 7)) << 4);
    *(uint4*)((char*)hi + off) = make_uint4(hw[0], hw[1], hw[2], hw[3]);
}

struct ConvArgs {
    const float* src[4];
    __half* hi[4];
};

__global__ __launch_bounds__(256)
void conv_act(ConvArgs a)   // grid (4096, 3)
{
    const int z = blockIdx.y;
    const int gid = blockIdx.x * 256 + threadIdx.x;
    round_store(a.src[z], a.hi[z], gid);
}

__global__ __launch_bounds__(256)
void conv_w(ConvArgs a)     // grid (512, 4)
{
    const int z = blockIdx.y;
    const int gid = blockIdx.x * 256 + threadIdx.x;
    round_store(a.src[z], a.hi[z], gid);
}

// ---------------------------------------------------------------------------
// 1-term fp16 HMMA GEMM: C ~= Ah·Bh^T + bias
// Tile 128x128, K-chunk 64, 3-stage bulk-copy pipeline, 8 warps (4m x 2n),
// 2 CTAs/SM (stage = 2 x 16KB tiles -> 97KB smem).
// ---------------------------------------------------------------------------
#define STAGEB (2 * TILEB)              // 32768
#define GSMEM  (1024 + 3 * STAGEB)      // 99328

__device__ __forceinline__
void gemm_core1(const __half* __restrict__ Ah, const __half* __restrict__ Bh,
                const float* __restrict__ bias, float* __restrict__ C,
                char* smem)
{
    const uint32_t sb = smem_u32(smem);
    const int tid = threadIdx.x;
    const int wid = tid >> 5, lane = tid & 31;
    const int ntb = blockIdx.x, mtb = blockIdx.y;
    const int wm = wid >> 1, wn = wid & 1;

    if (tid == 0) {
        MBAR_INIT(sb + 0, 1);
        MBAR_INIT(sb + 8, 1);
        MBAR_INIT(sb + 16, 1);
    }
    __syncthreads();

    const uint32_t st0 = sb + 1024;
    const char* aH = (const char*)Ah + ((size_t)mtb * 16 << 14);
    const char* bH = (const char*)Bh + ((size_t)ntb * 16 << 14);

    auto load_stage = [&](int kc, int s) {
        const uint32_t full = sb + 8 * s;
        MBAR_EXPECT_TX(full, STAGEB);
        const uint32_t d = st0 + s * STAGEB;
        const size_t o = (size_t)kc << 14;
        bulk_g2s(d + 0 * TILEB, aH + o, TILEB, full);
        bulk_g2s(d + 1 * TILEB, bH + o, TILEB, full);
    };

    if (tid == 0) {
        load_stage(0, 0);
        load_stage(1, 1);
        load_stage(2, 2);
    }

    float acc[2][8][4];
#pragma unroll
    for (int a = 0; a < 2; a++)
#pragma unroll
        for (int b = 0; b < 8; b++)
#pragma unroll
            for (int c = 0; c < 4; c++) acc[a][b][c] = 0.0f;

    const uint32_t la7 = lane & 7;
    const uint32_t a_row = (uint32_t)(wm * 32 + (lane & 15)) * 128;
    const uint32_t a_sel = (lane >> 4);
    const uint32_t b_row = (uint32_t)(wn * 64 + ((lane >> 4) & 1) * 8 + (lane & 7)) * 128;
    const uint32_t b_sel = ((lane >> 3) & 1);

    int s = 0, par = 0;
    for (int kc = 0; kc < 16; kc++) {
        MBAR_WAIT(sb + 8 * s, par);

        const uint32_t st = st0 + s * STAGEB;
        const uint32_t tAH = st + 0 * TILEB;
        const uint32_t tBH = st + 1 * TILEB;

#pragma unroll
        for (int ks = 0; ks < 4; ks++) {
            const uint32_t ca = ((uint32_t)(ks * 2) + a_sel) ^ la7;
            const uint32_t cb = ((uint32_t)(ks * 2) + b_sel) ^ la7;
            uint32_t ah[2][4], bh[4][4];
#pragma unroll
            for (int m2 = 0; m2 < 2; m2++)
                LDSM4(ah[m2], tAH + a_row + m2 * 2048 + ca * 16);
#pragma unroll
            for (int n2 = 0; n2 < 4; n2++)
                LDSM4(bh[n2], tBH + b_row + n2 * 2048 + cb * 16);
#pragma unroll
            for (int m2 = 0; m2 < 2; m2++)
#pragma unroll
                for (int n2 = 0; n2 < 4; n2++) {
                    MMA16816(acc[m2][n2 * 2 + 0], ah[m2], bh[n2][0], bh[n2][1]);
                    MMA16816(acc[m2][n2 * 2 + 1], ah[m2], bh[n2][2], bh[n2][3]);
                }
        }
        __syncthreads();
        if (tid == 0 && kc + 3 < 16) load_stage(kc + 3, s);
        if (++s == 3) { s = 0; par ^= 1; }
    }

    const int rbase = mtb * 128 + wm * 32 + (lane >> 2);
    const int cbase = ntb * 128 + wn * 64 + (lane & 3) * 2;
#pragma unroll
    for (int m2 = 0; m2 < 2; m2++)
#pragma unroll
        for (int nt2 = 0; nt2 < 8; nt2++) {
            const int col = cbase + nt2 * 8;
            const float b0 = bias[col], b1 = bias[col + 1];
            float* p0 = C + (size_t)(rbase + m2 * 16) * EMB_ + col;
            float* p1 = p0 + 8 * EMB_;
            *(float2*)p0 = make_float2(acc[m2][nt2][0] + b0, acc[m2][nt2][1] + b1);
            *(float2*)p1 = make_float2(acc[m2][nt2][2] + b0, acc[m2][nt2][3] + b1);
        }
}

struct QKVArgs {
    const __half* ah[3];
    const __half* bh[3];
    const float*  bias[3];
    float*        c[3];
};

__global__ __launch_bounds__(256, 2)
void gemm_qkv(QKVArgs a)
{
    extern __shared__ char smem[];
    const int z = blockIdx.z;
    gemm_core1(a.ah[z], a.bh[z], a.bias[z], a.c[z], smem);
}

__global__ __launch_bounds__(256, 2)
void gemm_o(const __half* __restrict__ ah, const __half* __restrict__ bh,
            const float* __restrict__ bias, float* __restrict__ c)
{
    extern __shared__ char smem[];
    gemm_core1(ah, bh, bias, c, smem);
}

// ---------------------------------------------------------------------------
// Per-token head-axis attention (fp32 in, tiled-swizzled fp16 out).
// No K transpose: score phase reads sq/sk rows directly (float4, 2x2 block).
// ---------------------------------------------------------------------------
__global__ __launch_bounds__(256)
void attn_head_mix(const float* __restrict__ q, const float* __restrict__ k,
                   const float* __restrict__ v, __half* __restrict__ oh)
{
    __shared__ float sq[NHEAD][68];
    __shared__ float sk[NHEAD][68];
    __shared__ float sv[NHEAD][68];
    __shared__ float sa[NHEAD * NHEAD];

    const int t = blockIdx.x;
    const int tid = threadIdx.x;
    const size_t base = (size_t)t * EMB_;

    {
        const int e0 = tid * 4;
        const int h = e0 >> 6, d0 = e0 & 63;
        *(float4*)&sq[h][d0] = *(const float4*)(q + base + e0);
        *(float4*)&sk[h][d0] = *(const float4*)(k + base + e0);
        *(float4*)&sv[h][d0] = *(const float4*)(v + base + e0);
    }
    __syncthreads();

    if (tid < 64) {
        const int h0 = (tid >> 3) << 1;
        const int g0 = (tid & 7) << 1;
        float s00 = 0.f, s01 = 0.f, s10 = 0.f, s11 = 0.f;
#pragma unroll
        for (int d = 0; d < HDIM; d += 4) {
            const float4 qa = *(const float4*)&sq[h0][d];
            const float4 qb = *(const float4*)&sq[h0 + 1][d];
            const float4 ka = *(const float4*)&sk[g0][d];
            const float4 kb = *(const float4*)&sk[g0 + 1][d];
            s00 = fmaf(qa.x, ka.x, s00); s00 = fmaf(qa.y, ka.y, s00);
            s00 = fmaf(qa.z, ka.z, s00); s00 = fmaf(qa.w, ka.w, s00);
            s01 = fmaf(qa.x, kb.x, s01); s01 = fmaf(qa.y, kb.y, s01);
            s01 = fmaf(qa.z, kb.z, s01); s01 = fmaf(qa.w, kb.w, s01);
            s10 = fmaf(qb.x, ka.x, s10); s10 = fmaf(qb.y, ka.y, s10);
            s10 = fmaf(qb.z, ka.z, s10); s10 = fmaf(qb.w, ka.w, s10);
            s11 = fmaf(qb.x, kb.x, s11); s11 = fmaf(qb.y, kb.y, s11);
            s11 = fmaf(qb.z, kb.z, s11); s11 = fmaf(qb.w, kb.w, s11);
        }
        s00 *= 0.125f; s01 *= 0.125f; s10 *= 0.125f; s11 *= 0.125f;

        float m0 = fmaxf(s00, s01), m1 = fmaxf(s10, s11);
#pragma unroll
        for (int o = 4; o > 0; o >>= 1) {
            m0 = fmaxf(m0, __shfl_xor_sync(0xffffffffu, m0, o, 8));
            m1 = fmaxf(m1, __shfl_xor_sync(0xffffffffu, m1, o, 8));
        }
        const float e00 = __expf(s00 - m0), e01 = __expf(s01 - m0);
        const float e10 = __expf(s10 - m1), e11 = __expf(s11 - m1);
        float u0 = e00 + e01, u1 = e10 + e11;
#pragma unroll
        for (int o = 4; o > 0; o >>= 1) {
            u0 += __shfl_xor_sync(0xffffffffu, u0, o, 8);
            u1 += __shfl_xor_sync(0xffffffffu, u1, o, 8);
        }
        const float r0 = 1.0f / u0, r1 = 1.0f / u1;
        sa[h0 * 16 + g0]           = e00 * r0;
        sa[h0 * 16 + g0 + 1]       = e01 * r0;
        sa[(h0 + 1) * 16 + g0]     = e10 * r1;
        sa[(h0 + 1) * 16 + g0 + 1] = e11 * r1;
    }
    __syncthreads();

    const int ho = tid >> 4;
    const int d0 = (tid & 15) * 4;
    float o4[4] = {0.f, 0.f, 0.f, 0.f};
#pragma unroll
    for (int gg = 0; gg < NHEAD; gg++) {
        const float a = sa[ho * 16 + gg];
        float4 vv = *(const float4*)&sv[gg][d0];
        o4[0] = fmaf(a, vv.x, o4[0]);
        o4[1] = fmaf(a, vv.y, o4[1]);
        o4[2] = fmaf(a, vv.z, o4[2]);
        o4[3] = fmaf(a, vv.w, o4[3]);
    }

    ushort4 hv;
    hv.x = __half_as_ushort(__float2half_rn(o4[0]));
    hv.y = __half_as_ushort(__float2half_rn(o4[1]));
    hv.z = __half_as_ushort(__float2half_rn(o4[2]));
    hv.w = __half_as_ushort(__float2half_rn(o4[3]));

    const int chunk = d0 >> 3;
    const size_t off = (((size_t)(t >> 7) * 16 + ho) << 14)
                     + (t & 127) * 128 + ((chunk ^ (t & 7)) << 4) + (d0 & 7) * 2;
    *(ushort4*)((char*)oh + off) = hv;
}

// ---------------------------------------------------------------------------
// Launch
// ---------------------------------------------------------------------------
extern "C" void kernel_launch(void* const* d_in, const int* in_sizes, int n_in,
                              void* d_out, int out_size)
{
    const float* values = (const float*)d_in[0];
    const float* keys   = (const float*)d_in[1];
    const float* query  = (const float*)d_in[2];
    const float* Wv = (const float*)d_in[3];
    const float* bv = (const float*)d_in[4];
    const float* Wk = (const float*)d_in[5];
    const float* bk = (const float*)d_in[6];
    const float* Wq = (const float*)d_in[7];
    const float* bq = (const float*)d_in[8];
    const float* Wo = (const float*)d_in[9];
    const float* bo = (const float*)d_in[10];
    float* out = (float*)d_out;

    static bool attr_set = false;
    if (!attr_set) {
        cudaFuncSetAttribute(gemm_qkv,
                             cudaFuncAttributeMaxDynamicSharedMemorySize, GSMEM);
        cudaFuncSetAttribute(gemm_o,
                             cudaFuncAttributeMaxDynamicSharedMemorySize, GSMEM);
        attr_set = true;
    }

    __half *vh, *kh, *qh, *wvh, *wkh, *wqh, *woh, *ah;
    float *gv, *gk, *gq;
    cudaGetSymbolAddress((void**)&vh, g_vh);
    cudaGetSymbolAddress((void**)&kh, g_kh);
    cudaGetSymbolAddress((void**)&qh, g_qh);
    cudaGetSymbolAddress((void**)&wvh, g_wvh);
    cudaGetSymbolAddress((void**)&wkh, g_wkh);
    cudaGetSymbolAddress((void**)&wqh, g_wqh);
    cudaGetSymbolAddress((void**)&woh, g_woh);
    cudaGetSymbolAddress((void**)&ah, g_ah);
    cudaGetSymbolAddress((void**)&gv, g_v);
    cudaGetSymbolAddress((void**)&gk, g_k);
    cudaGetSymbolAddress((void**)&gq, g_q);

    ConvArgs ca;
    ca.src[0] = values; ca.hi[0] = vh;
    ca.src[1] = keys;   ca.hi[1] = kh;
    ca.src[2] = query;  ca.hi[2] = qh;
    ca.src[3] = nullptr; ca.hi[3] = nullptr;
    conv_act<<<dim3(TOK * 128 / 256, 3), 256>>>(ca);

    ConvArgs cw;
    cw.src[0] = Wq; cw.hi[0] = wqh;
    cw.src[1] = Wk; cw.hi[1] = wkh;
    cw.src[2] = Wv; cw.hi[2] = wvh;
    cw.src[3] = Wo; cw.hi[3] = woh;
    conv_w<<<dim3(EMB_ * 128 / 256, 4), 256>>>(cw);

    QKVArgs a;
    a.ah[0] = qh; a.bh[0] = wqh; a.bias[0] = bq; a.c[0] = gq;
    a.ah[1] = kh; a.bh[1] = wkh; a.bias[1] = bk; a.c[1] = gk;
    a.ah[2] = vh; a.bh[2] = wvh; a.bias[2] = bv; a.c[2] = gv;
    dim3 ggrid(EMB_ / 128, TOK / 128, 3);   // (8, 64, 3)
    gemm_qkv<<<ggrid, 256, GSMEM>>>(a);

    attn_head_mix<<<TOK, 256>>>(gq, gk, gv, ah);

    dim3 ogrid(EMB_ / 128, TOK / 128);      // (8, 64)
    gemm_o<<<ogrid, 256, GSMEM>>>(ah, woh, bo, out);
}

// round 9
// speedup vs baseline: 1.8040x; 1.0563x over previous
#include <cuda_runtime.h>
#include <cuda_fp16.h>
#include <cstdint>

// Problem constants (B=4, S=2048, EMB=1024, HEADS=16, HEAD_DIM=64)
#define TOK   8192
#define EMB_  1024
#define NHEAD 16
#define HDIM  64
#define TILEB 16384          // one 128-row x 128-byte (64 fp16) tile

// ---------------------------------------------------------------------------
// Scratch (device globals). Tiled-swizzled fp16 (GEMM operand layout):
// element (row, col) -> tile (row>>7, col>>6), inside: byte
//   (row&127)*128 + (((col&63)>>3) ^ (row&7))*16 + (col&7)*2
// Plus fp16 row-major q/k/v intermediates.
// ---------------------------------------------------------------------------
__device__ __half g_vh[TOK * EMB_];     // conv(values)     - GEMM A, swizzled
__device__ __half g_kh[TOK * EMB_];     // conv(keys)
__device__ __half g_qh[TOK * EMB_];     // conv(query)
__device__ __half g_wvh[EMB_ * EMB_];
__device__ __half g_wkh[EMB_ * EMB_];
__device__ __half g_wqh[EMB_ * EMB_];
__device__ __half g_woh[EMB_ * EMB_];
__device__ __half g_ah[TOK * EMB_];     // attention out    - GEMM A, swizzled
__device__ __half g_vo[TOK * EMB_];     // v projection out - row-major fp16
__device__ __half g_ko[TOK * EMB_];
__device__ __half g_qo[TOK * EMB_];

// ---------------------------------------------------------------------------
// PTX helpers
// ---------------------------------------------------------------------------
__device__ __forceinline__ uint32_t smem_u32(const void* p) {
    uint32_t a;
    asm("{ .reg .u64 t; cvta.to.shared.u64 t, %1; cvt.u32.u64 %0, t; }"
        : "=r"(a) : "l"(p));
    return a;
}

#define MBAR_INIT(addr, cnt) \
    asm volatile("mbarrier.init.shared.b64 [%0], %1;" :: "r"(addr), "r"(cnt) : "memory")
#define MBAR_EXPECT_TX(addr, bytes) \
    asm volatile("mbarrier.arrive.expect_tx.shared.b64 _, [%0], %1;" \
                 :: "r"(addr), "r"(bytes) : "memory")
#define MBAR_WAIT(addr, parity) do { \
    uint32_t _m = (addr), _p = (parity), _done; \
    asm volatile("{ .reg .pred p; mbarrier.try_wait.parity.acquire.cta.shared::cta.b64 p, [%1], %2; selp.b32 %0, 1, 0, p; }" \
                 : "=r"(_done) : "r"(_m), "r"(_p) : "memory"); \
    if (!_done) { \
        asm volatile("{ .reg .pred P1; WL_%=: mbarrier.try_wait.parity.acquire.cta.shared::cta.b64 P1, [%0], %1, 0x989680; @P1 bra.uni WD_%=; bra.uni WL_%=; WD_%=: }" \
                     :: "r"(_m), "r"(_p) : "memory"); \
    } \
} while (0)

__device__ __forceinline__ void bulk_g2s(uint32_t dst, const void* src,
                                         uint32_t bytes, uint32_t mbar) {
    asm volatile(
        "cp.async.bulk.shared::cluster.global.mbarrier::complete_tx::bytes [%0], [%1], %2, [%3];"
        :: "r"(dst), "l"(src), "r"(bytes), "r"(mbar) : "memory");
}

#define LDSM4(R, addr) \
    asm volatile("ldmatrix.sync.aligned.m8n8.x4.shared.b16 {%0,%1,%2,%3}, [%4];" \
        : "=r"((R)[0]), "=r"((R)[1]), "=r"((R)[2]), "=r"((R)[3]) : "r"(addr))

#define MMA16816(D, A, B0, B1) \
    asm volatile("mma.sync.aligned.m16n8k16.row.col.f32.f16.f16.f32 " \
        "{%0,%1,%2,%3}, {%4,%5,%6,%7}, {%8,%9}, {%0,%1,%2,%3};" \
        : "+f"((D)[0]), "+f"((D)[1]), "+f"((D)[2]), "+f"((D)[3]) \
        : "r"((A)[0]), "r"((A)[1]), "r"((A)[2]), "r"((A)[3]), "r"(B0), "r"(B1))

// ---------------------------------------------------------------------------
// Conversion: fp32 row-major -> fp16 (round) in tiled-swizzled layout.
// ---------------------------------------------------------------------------
__device__ __forceinline__ void round_store(const float* __restrict__ src,
                                            __half* __restrict__ hi, int gid)
{
    const int row = gid >> 7;
    const int chunk = gid & 127;
    const int col0 = chunk << 3;
    const int kc = col0 >> 6;
    const int c16 = (col0 >> 3) & 7;

    const float4* sp = (const float4*)(src + (size_t)row * EMB_ + col0);
    float x[8];
    *(float4*)&x[0] = sp[0];
    *(float4*)&x[4] = sp[1];

    uint32_t hw[4];
#pragma unroll
    for (int i = 0; i < 4; i++) {
        __half h0 = __float2half_rn(x[2 * i]);
        __half h1 = __float2half_rn(x[2 * i + 1]);
        hw[i] = (uint32_t)__half_as_ushort(h0) | ((uint32_t)__half_as_ushort(h1) << 16);
    }
    const size_t off = (((size_t)(row >> 7) * 16 + kc) << 14)
                     + (row & 127) * 128 + ((c16 ^ (row & 7)) << 4);
    *(uint4*)((char*)hi + off) = make_uint4(hw[0], hw[1], hw[2], hw[3]);
}

struct ConvArgs {
    const float* src[4];
    __half* hi[4];
};

__global__ __launch_bounds__(256)
void conv_act(ConvArgs a)   // grid (4096, 3)
{
    const int z = blockIdx.y;
    const int gid = blockIdx.x * 256 + threadIdx.x;
    round_store(a.src[z], a.hi[z], gid);
}

__global__ __launch_bounds__(256)
void conv_w(ConvArgs a)     // grid (512, 4)
{
    const int z = blockIdx.y;
    const int gid = blockIdx.x * 256 + threadIdx.x;
    round_store(a.src[z], a.hi[z], gid);
}

// ---------------------------------------------------------------------------
// 1-term fp16 HMMA GEMM core. Tile 128x128, K-chunk 64, 3-stage bulk pipeline,
// 8 warps (4m x 2n), 2 CTAs/SM. Epilogue templated on output type.
// OUT==0: fp32 C; OUT==1: fp16 C (row-major).
// ---------------------------------------------------------------------------
#define STAGEB (2 * TILEB)              // 32768
#define GSMEM  (1024 + 3 * STAGEB)      // 99328

template <int OUT>
__device__ __forceinline__
void gemm_core1(const __half* __restrict__ Ah, const __half* __restrict__ Bh,
                const float* __restrict__ bias, void* __restrict__ Cv,
                char* smem)
{
    const uint32_t sb = smem_u32(smem);
    const int tid = threadIdx.x;
    const int wid = tid >> 5, lane = tid & 31;
    const int ntb = blockIdx.x, mtb = blockIdx.y;
    const int wm = wid >> 1, wn = wid & 1;

    if (tid == 0) {
        MBAR_INIT(sb + 0, 1);
        MBAR_INIT(sb + 8, 1);
        MBAR_INIT(sb + 16, 1);
    }
    __syncthreads();

    const uint32_t st0 = sb + 1024;
    const char* aH = (const char*)Ah + ((size_t)mtb * 16 << 14);
    const char* bH = (const char*)Bh + ((size_t)ntb * 16 << 14);

    auto load_stage = [&](int kc, int s) {
        const uint32_t full = sb + 8 * s;
        MBAR_EXPECT_TX(full, STAGEB);
        const uint32_t d = st0 + s * STAGEB;
        const size_t o = (size_t)kc << 14;
        bulk_g2s(d + 0 * TILEB, aH + o, TILEB, full);
        bulk_g2s(d + 1 * TILEB, bH + o, TILEB, full);
    };

    if (tid == 0) {
        load_stage(0, 0);
        load_stage(1, 1);
        load_stage(2, 2);
    }

    float acc[2][8][4];
#pragma unroll
    for (int a = 0; a < 2; a++)
#pragma unroll
        for (int b = 0; b < 8; b++)
#pragma unroll
            for (int c = 0; c < 4; c++) acc[a][b][c] = 0.0f;

    const uint32_t la7 = lane & 7;
    const uint32_t a_row = (uint32_t)(wm * 32 + (lane & 15)) * 128;
    const uint32_t a_sel = (lane >> 4);
    const uint32_t b_row = (uint32_t)(wn * 64 + ((lane >> 4) & 1) * 8 + (lane & 7)) * 128;
    const uint32_t b_sel = ((lane >> 3) & 1);

    int s = 0, par = 0;
    for (int kc = 0; kc < 16; kc++) {
        MBAR_WAIT(sb + 8 * s, par);

        const uint32_t st = st0 + s * STAGEB;
        const uint32_t tAH = st + 0 * TILEB;
        const uint32_t tBH = st + 1 * TILEB;

#pragma unroll
        for (int ks = 0; ks < 4; ks++) {
            const uint32_t ca = ((uint32_t)(ks * 2) + a_sel) ^ la7;
            const uint32_t cb = ((uint32_t)(ks * 2) + b_sel) ^ la7;
            uint32_t ah[2][4], bh[4][4];
#pragma unroll
            for (int m2 = 0; m2 < 2; m2++)
                LDSM4(ah[m2], tAH + a_row + m2 * 2048 + ca * 16);
#pragma unroll
            for (int n2 = 0; n2 < 4; n2++)
                LDSM4(bh[n2], tBH + b_row + n2 * 2048 + cb * 16);
#pragma unroll
            for (int m2 = 0; m2 < 2; m2++)
#pragma unroll
                for (int n2 = 0; n2 < 4; n2++) {
                    MMA16816(acc[m2][n2 * 2 + 0], ah[m2], bh[n2][0], bh[n2][1]);
                    MMA16816(acc[m2][n2 * 2 + 1], ah[m2], bh[n2][2], bh[n2][3]);
                }
        }
        __syncthreads();
        if (tid == 0 && kc + 3 < 16) load_stage(kc + 3, s);
        if (++s == 3) { s = 0; par ^= 1; }
    }

    const int rbase = mtb * 128 + wm * 32 + (lane >> 2);
    const int cbase = ntb * 128 + wn * 64 + (lane & 3) * 2;
#pragma unroll
    for (int m2 = 0; m2 < 2; m2++)
#pragma unroll
        for (int nt2 = 0; nt2 < 8; nt2++) {
            const int col = cbase + nt2 * 8;
            const float b0 = bias[col], b1 = bias[col + 1];
            const float v00 = acc[m2][nt2][0] + b0, v01 = acc[m2][nt2][1] + b1;
            const float v10 = acc[m2][nt2][2] + b0, v11 = acc[m2][nt2][3] + b1;
            if (OUT == 0) {
                float* C = (float*)Cv;
                float* p0 = C + (size_t)(rbase + m2 * 16) * EMB_ + col;
                *(float2*)p0 = make_float2(v00, v01);
                *(float2*)(p0 + 8 * EMB_) = make_float2(v10, v11);
            } else {
                __half* C = (__half*)Cv;
                __half* p0 = C + (size_t)(rbase + m2 * 16) * EMB_ + col;
                __half2* h0 = (__half2*)p0;
                __half2* h1 = (__half2*)(p0 + 8 * EMB_);
                *h0 = __floats2half2_rn(v00, v01);
                *h1 = __floats2half2_rn(v10, v11);
            }
        }
}

struct QKVArgs {
    const __half* ah[3];
    const __half* bh[3];
    const float*  bias[3];
    __half*       c[3];
};

__global__ __launch_bounds__(256, 2)
void gemm_qkv(QKVArgs a)
{
    extern __shared__ char smem[];
    const int z = blockIdx.z;
    gemm_core1<1>(a.ah[z], a.bh[z], a.bias[z], a.c[z], smem);
}

__global__ __launch_bounds__(256, 2)
void gemm_o(const __half* __restrict__ ah, const __half* __restrict__ bh,
            const float* __restrict__ bias, float* __restrict__ c)
{
    extern __shared__ char smem[];
    gemm_core1<0>(ah, bh, bias, c, smem);
}

// ---------------------------------------------------------------------------
// Per-token head-axis attention, fp16 in (row-major), fp16 swizzled out.
// smem rows padded to 144B (9 x 16B banks).
// ---------------------------------------------------------------------------
__global__ __launch_bounds__(256)
void attn_head_mix(const __half* __restrict__ q, const __half* __restrict__ k,
                   const __half* __restrict__ v, __half* __restrict__ oh)
{
    __shared__ __half sq[NHEAD][72];
    __shared__ __half sk[NHEAD][72];
    __shared__ __half sv[NHEAD][72];
    __shared__ float sa[NHEAD * NHEAD];

    const int t = blockIdx.x;
    const int tid = threadIdx.x;
    const size_t base = (size_t)t * EMB_;

    // 256 threads x 4 halves per array (8B loads, fully coalesced).
    {
        const int e0 = tid * 4;
        const int h = e0 >> 6, d0 = e0 & 63;
        *(uint2*)&sq[h][d0] = *(const uint2*)(q + base + e0);
        *(uint2*)&sk[h][d0] = *(const uint2*)(k + base + e0);
        *(uint2*)&sv[h][d0] = *(const uint2*)(v + base + e0);
    }
    __syncthreads();

    if (tid < 64) {
        const int h0 = (tid >> 3) << 1;
        const int g0 = (tid & 7) << 1;
        float s00 = 0.f, s01 = 0.f, s10 = 0.f, s11 = 0.f;
#pragma unroll
        for (int d = 0; d < HDIM; d += 2) {
            const float2 qa = __half22float2(*(const __half2*)&sq[h0][d]);
            const float2 qb = __half22float2(*(const __half2*)&sq[h0 + 1][d]);
            const float2 ka = __half22float2(*(const __half2*)&sk[g0][d]);
            const float2 kb = __half22float2(*(const __half2*)&sk[g0 + 1][d]);
            s00 = fmaf(qa.x, ka.x, s00); s00 = fmaf(qa.y, ka.y, s00);
            s01 = fmaf(qa.x, kb.x, s01); s01 = fmaf(qa.y, kb.y, s01);
            s10 = fmaf(qb.x, ka.x, s10); s10 = fmaf(qb.y, ka.y, s10);
            s11 = fmaf(qb.x, kb.x, s11); s11 = fmaf(qb.y, kb.y, s11);
        }
        s00 *= 0.125f; s01 *= 0.125f; s10 *= 0.125f; s11 *= 0.125f;

        float m0 = fmaxf(s00, s01), m1 = fmaxf(s10, s11);
#pragma unroll
        for (int o = 4; o > 0; o >>= 1) {
            m0 = fmaxf(m0, __shfl_xor_sync(0xffffffffu, m0, o, 8));
            m1 = fmaxf(m1, __shfl_xor_sync(0xffffffffu, m1, o, 8));
        }
        const float e00 = __expf(s00 - m0), e01 = __expf(s01 - m0);
        const float e10 = __expf(s10 - m1), e11 = __expf(s11 - m1);
        float u0 = e00 + e01, u1 = e10 + e11;
#pragma unroll
        for (int o = 4; o > 0; o >>= 1) {
            u0 += __shfl_xor_sync(0xffffffffu, u0, o, 8);
            u1 += __shfl_xor_sync(0xffffffffu, u1, o, 8);
        }
        const float r0 = 1.0f / u0, r1 = 1.0f / u1;
        sa[h0 * 16 + g0]           = e00 * r0;
        sa[h0 * 16 + g0 + 1]       = e01 * r0;
        sa[(h0 + 1) * 16 + g0]     = e10 * r1;
        sa[(h0 + 1) * 16 + g0 + 1] = e11 * r1;
    }
    __syncthreads();

    const int ho = tid >> 4;
    const int d0 = (tid & 15) * 4;
    float o4[4] = {0.f, 0.f, 0.f, 0.f};
#pragma unroll
    for (int gg = 0; gg < NHEAD; gg++) {
        const float a = sa[ho * 16 + gg];
        const float2 v0 = __half22float2(*(const __half2*)&sv[gg][d0]);
        const float2 v1 = __half22float2(*(const __half2*)&sv[gg][d0 + 2]);
        o4[0] = fmaf(a, v0.x, o4[0]);
        o4[1] = fmaf(a, v0.y, o4[1]);
        o4[2] = fmaf(a, v1.x, o4[2]);
        o4[3] = fmaf(a, v1.y, o4[3]);
    }

    ushort4 hv;
    hv.x = __half_as_ushort(__float2half_rn(o4[0]));
    hv.y = __half_as_ushort(__float2half_rn(o4[1]));
    hv.z = __half_as_ushort(__float2half_rn(o4[2]));
    hv.w = __half_as_ushort(__float2half_rn(o4[3]));

    const int chunk = d0 >> 3;
    const size_t off = (((size_t)(t >> 7) * 16 + ho) << 14)
                     + (t & 127) * 128 + ((chunk ^ (t & 7)) << 4) + (d0 & 7) * 2;
    *(ushort4*)((char*)oh + off) = hv;
}

// ---------------------------------------------------------------------------
// Launch
// ---------------------------------------------------------------------------
extern "C" void kernel_launch(void* const* d_in, const int* in_sizes, int n_in,
                              void* d_out, int out_size)
{
    const float* values = (const float*)d_in[0];
    const float* keys   = (const float*)d_in[1];
    const float* query  = (const float*)d_in[2];
    const float* Wv = (const float*)d_in[3];
    const float* bv = (const float*)d_in[4];
    const float* Wk = (const float*)d_in[5];
    const float* bk = (const float*)d_in[6];
    const float* Wq = (const float*)d_in[7];
    const float* bq = (const float*)d_in[8];
    const float* Wo = (const float*)d_in[9];
    const float* bo = (const float*)d_in[10];
    float* out = (float*)d_out;

    static bool attr_set = false;
    if (!attr_set) {
        cudaFuncSetAttribute(gemm_qkv,
                             cudaFuncAttributeMaxDynamicSharedMemorySize, GSMEM);
        cudaFuncSetAttribute(gemm_o,
                             cudaFuncAttributeMaxDynamicSharedMemorySize, GSMEM);
        attr_set = true;
    }

    __half *vh, *kh, *qh, *wvh, *wkh, *wqh, *woh, *ah, *vo, *ko, *qo;
    cudaGetSymbolAddress((void**)&vh, g_vh);
    cudaGetSymbolAddress((void**)&kh, g_kh);
    cudaGetSymbolAddress((void**)&qh, g_qh);
    cudaGetSymbolAddress((void**)&wvh, g_wvh);
    cudaGetSymbolAddress((void**)&wkh, g_wkh);
    cudaGetSymbolAddress((void**)&wqh, g_wqh);
    cudaGetSymbolAddress((void**)&woh, g_woh);
    cudaGetSymbolAddress((void**)&ah, g_ah);
    cudaGetSymbolAddress((void**)&vo, g_vo);
    cudaGetSymbolAddress((void**)&ko, g_ko);
    cudaGetSymbolAddress((void**)&qo, g_qo);

    ConvArgs ca;
    ca.src[0] = values; ca.hi[0] = vh;
    ca.src[1] = keys;   ca.hi[1] = kh;
    ca.src[2] = query;  ca.hi[2] = qh;
    ca.src[3] = nullptr; ca.hi[3] = nullptr;
    conv_act<<<dim3(TOK * 128 / 256, 3), 256>>>(ca);

    ConvArgs cw;
    cw.src[0] = Wq; cw.hi[0] = wqh;
    cw.src[1] = Wk; cw.hi[1] = wkh;
    cw.src[2] = Wv; cw.hi[2] = wvh;
    cw.src[3] = Wo; cw.hi[3] = woh;
    conv_w<<<dim3(EMB_ * 128 / 256, 4), 256>>>(cw);

    QKVArgs a;
    a.ah[0] = qh; a.bh[0] = wqh; a.bias[0] = bq; a.c[0] = qo;
    a.ah[1] = kh; a.bh[1] = wkh; a.bias[1] = bk; a.c[1] = ko;
    a.ah[2] = vh; a.bh[2] = wvh; a.bias[2] = bv; a.c[2] = vo;
    dim3 ggrid(EMB_ / 128, TOK / 128, 3);   // (8, 64, 3)
    gemm_qkv<<<ggrid, 256, GSMEM>>>(a);

    attn_head_mix<<<TOK, 256>>>(qo, ko, vo, ah);

    dim3 ogrid(EMB_ / 128, TOK / 128);      // (8, 64)
    gemm_o<<<ogrid, 256, GSMEM>>>(ah, woh, bo, out);
}